// round 5
// baseline (speedup 1.0000x reference)
#include <cuda_runtime.h>
#include <cuda_fp16.h>

// Problem constants
#define BB 8
#define CC 4
#define DD 128
#define HH 128
#define WW 128
#define FDIM 512
#define VOL (1<<21)          // 128^3

// Per-batch affine coefficients: integer (w,h,d) -> (ix,iy,iz)
__device__ float g_A[BB * 12];

// Scratch: per voxel slot = {c0c1@z, c2c3@z, c0c1@z+1, c2c3@z+1} as 8 fp16 = 16B.
// One LDG.128 fetches both z-corners for all 4 channels.
__device__ uint4 g_scr[(size_t)BB * VOL];

static __device__ __forceinline__ unsigned pack2(float a, float b) {
    __half2 h = __floats2half2_rn(a, b);
    return *reinterpret_cast<unsigned*>(&h);
}

// Packed f32x2 ops (Blackwell): one instruction, two fp32 lanes.
#define MUL_F32X2(out, a, b) \
    asm("mul.rn.f32x2 %0, %1, %2;" : "=l"(out) : "l"(a), "l"(b))
#define FMA_F32X2(d, a, b, c) \
    asm("fma.rn.f32x2 %0, %1, %2, %3;" : "=l"(d) : "l"(a), "l"(b), "l"(c))
#define PACK_F32X2(out, lo, hi) \
    asm("mov.b64 %0, {%1, %2};" : "=l"(out) : "f"(lo), "f"(hi))
#define UNPACK_F32X2(lo, hi, in) \
    asm("mov.b64 {%0, %1}, %2;" : "=f"(lo), "=f"(hi) : "l"(in))

// ---------------------------------------------------------------------------
// Kernel 1: prep. Block 0 computes per-batch affine coefficients.
// All blocks build the z-pair fp16 channel-packed scratch.
// Thread handles 4 consecutive voxels (same row => same z).
// ---------------------------------------------------------------------------
__global__ void __launch_bounds__(256)
prep_kernel(const float* __restrict__ x,
            const float* __restrict__ im_feat,
            const float* __restrict__ pos_w,
            const float* __restrict__ pos_b) {
    if (blockIdx.x == 0) {
        const int wid = threadIdx.x >> 5;
        const int lane = threadIdx.x & 31;
        if (wid < BB) {
            float pm = 0.f, pr = 0.f;
            for (int j = lane; j < FDIM; j += 32) {
                float f = im_feat[wid * FDIM + j];
                pm = fmaf(f, pos_w[j], pm);
                pr = fmaf(f, pos_w[FDIM + j], pr);
            }
            #pragma unroll
            for (int s = 16; s; s >>= 1) {
                pm += __shfl_xor_sync(0xffffffffu, pm, s);
                pr += __shfl_xor_sync(0xffffffffu, pr, s);
            }
            if (lane == 0) {
                float mu  = pm + pos_b[0];
                float rho = pr + pos_b[1];
                float cm = cosf(mu),  sm = sinf(mu);
                float cr = cosf(rho), sr = sinf(rho);
                const float SC = 128.0f / 127.0f;
                float* A = &g_A[wid * 12];
                float r0 = cm, r1 = sm * sr, r2 = -sm * cr;
                float r4 = cr, r5 = sr;
                float r6 = sm, r7 = -cm * sr, r8 = cm * cr;
                A[0] = r0 * SC;  A[1] = r1 * SC;  A[2] = r2 * SC;
                A[3] = 64.0f * (1.0f - (r0 + r1 + r2)) - 0.5f;
                A[4] = r4 * SC;  A[5] = r5 * SC;
                A[6] = 64.0f * (1.0f - (r4 + r5)) - 0.5f;
                A[7] = 0.0f;
                A[8] = r6 * SC;  A[9] = r7 * SC;  A[10] = r8 * SC;
                A[11] = 64.0f * (1.0f - (r6 + r7 + r8)) - 0.5f;
            }
        }
    }

    const size_t t = (size_t)blockIdx.x * 256 + threadIdx.x;  // < B*VOL/4
    const size_t s4 = t << 2;                                 // first voxel
    const size_t b = s4 >> 21;
    const unsigned v = (unsigned)(s4 & (VOL - 1));
    const unsigned z = v >> 14;
    const float* base = x + (b << 23);                        // b*C*VOL

    // plane z, 4 channels
    float4 p0 = *(const float4*)(base + v);
    float4 p1 = *(const float4*)(base + VOL + v);
    float4 p2 = *(const float4*)(base + 2u * VOL + v);
    float4 p3 = *(const float4*)(base + 3u * VOL + v);
    // plane z+1 (clamped: duplicate at z=127; value then paired with weight 0)
    const unsigned vn = v + ((z < DD - 1) ? (HH * WW) : 0);
    float4 q0 = *(const float4*)(base + vn);
    float4 q1 = *(const float4*)(base + VOL + vn);
    float4 q2 = *(const float4*)(base + 2u * VOL + vn);
    float4 q3 = *(const float4*)(base + 3u * VOL + vn);

    float a0[4] = {p0.x, p0.y, p0.z, p0.w};
    float a1[4] = {p1.x, p1.y, p1.z, p1.w};
    float a2[4] = {p2.x, p2.y, p2.z, p2.w};
    float a3[4] = {p3.x, p3.y, p3.z, p3.w};
    float b0[4] = {q0.x, q0.y, q0.z, q0.w};
    float b1[4] = {q1.x, q1.y, q1.z, q1.w};
    float b2[4] = {q2.x, q2.y, q2.z, q2.w};
    float b3[4] = {q3.x, q3.y, q3.z, q3.w};

    uint4* dst = g_scr + s4;
    #pragma unroll
    for (int j = 0; j < 4; ++j) {
        uint4 slot;
        slot.x = pack2(a0[j], a1[j]);   // c0,c1 @ z
        slot.y = pack2(a2[j], a3[j]);   // c2,c3 @ z
        slot.z = pack2(b0[j], b1[j]);   // c0,c1 @ z+1
        slot.w = pack2(b2[j], b3[j]);   // c2,c3 @ z+1
        dst[j] = slot;
    }
}

// ---------------------------------------------------------------------------
// Kernel 2: rotated trilinear grid_sample. 4 LDG.128 per voxel, each fetching
// an (x,y) column's full z-pair for all channels. f32x2 packed math.
// ---------------------------------------------------------------------------
__global__ void __launch_bounds__(256)
sample_kernel(float* __restrict__ out) {
    const int b = blockIdx.y;

    __shared__ float A[12];
    if (threadIdx.x < 12) A[threadIdx.x] = g_A[b * 12 + threadIdx.x];
    __syncthreads();

    const unsigned tid = blockIdx.x * 256 + threadIdx.x;   // < VOL
    const int w = tid & (WW - 1);
    const int h = (tid >> 7) & (HH - 1);
    const int d = tid >> 14;
    const float fw = (float)w, fh = (float)h, fd = (float)d;

    const float ix = fmaf(A[0], fw, fmaf(A[1], fh, fmaf(A[2],  fd, A[3])));
    const float iy =               fmaf(A[4], fh, fmaf(A[5],  fd, A[6]));
    const float iz = fmaf(A[8], fw, fmaf(A[9], fh, fmaf(A[10], fd, A[11])));

    const float fxf = floorf(ix), fyf = floorf(iy), fzf = floorf(iz);
    const int ix0 = (int)fxf, iy0 = (int)fyf, iz0 = (int)fzf;
    const float fx = ix - fxf, fy = iy - fyf, fz = iz - fzf;

    float wx0, wx1, wy0, wy1, wzA, wzB;
    int x0c, x1c, y0c, y1c, zs;

    const bool interior = (ix0 >= 0) & (ix0 < WW - 1) &
                          (iy0 >= 0) & (iy0 < HH - 1) &
                          (iz0 >= 0) & (iz0 < DD - 1);

    if (__all_sync(0xffffffffu, interior)) {
        wx0 = 1.0f - fx; wx1 = fx;
        wy0 = 1.0f - fy; wy1 = fy;
        wzA = 1.0f - fz; wzB = fz;
        x0c = ix0; x1c = ix0 + 1;
        y0c = iy0; y1c = iy0 + 1;
        zs = iz0;
    } else {
        const int x1 = ix0 + 1, y1 = iy0 + 1, z1 = iz0 + 1;
        wx0 = (ix0 >= 0 && ix0 < WW) ? (1.0f - fx) : 0.0f;
        wx1 = (x1  >= 0 && x1  < WW) ? fx          : 0.0f;
        wy0 = (iy0 >= 0 && iy0 < HH) ? (1.0f - fy) : 0.0f;
        wy1 = (y1  >= 0 && y1  < HH) ? fy          : 0.0f;
        const float wz0 = (iz0 >= 0 && iz0 < DD) ? (1.0f - fz) : 0.0f;
        const float wz1 = (z1  >= 0 && z1  < DD) ? fz          : 0.0f;
        x0c = min(max(ix0, 0), WW - 1);
        x1c = min(max(x1,  0), WW - 1);
        y0c = min(max(iy0, 0), HH - 1);
        y1c = min(max(y1,  0), HH - 1);
        zs  = min(max(iz0, 0), DD - 1);
        // slot at zs covers planes (zs, zs+1); remap weights onto slot halves
        wzA = (iz0 >= 0) ? wz0 : wz1;   // weight for slot's first plane
        wzB = (iz0 >= 0) ? wz1 : 0.0f;  // weight for slot's second plane
    }

    const uint4* p = g_scr + (((size_t)b << 21) | ((unsigned)zs << 14));
    const int yb0 = y0c << 7, yb1 = y1c << 7;

    const uint4 g00 = __ldg(p + (yb0 + x0c));
    const uint4 g01 = __ldg(p + (yb0 + x1c));
    const uint4 g10 = __ldg(p + (yb1 + x0c));
    const uint4 g11 = __ldg(p + (yb1 + x1c));

    unsigned long long WA, WB, acc01, acc23;
    PACK_F32X2(WA, wzA, wzA);
    PACK_F32X2(WB, wzB, wzB);
    {
        float z0f = 0.0f;
        PACK_F32X2(acc01, z0f, z0f);
        acc23 = acc01;
    }

    const float c00 = wx0 * wy0;
    const float c01 = wx1 * wy0;
    const float c10 = wx0 * wy1;
    const float c11 = wx1 * wy1;

    #define COLUMN(g, cwf)                                                     \
    {                                                                          \
        float2 a01 = __half22float2(*reinterpret_cast<const __half2*>(&g.x)); \
        float2 a23 = __half22float2(*reinterpret_cast<const __half2*>(&g.y)); \
        float2 b01 = __half22float2(*reinterpret_cast<const __half2*>(&g.z)); \
        float2 b23 = __half22float2(*reinterpret_cast<const __half2*>(&g.w)); \
        unsigned long long A01, A23, B01, B23, CW, m0, m1, t01, t23;          \
        PACK_F32X2(A01, a01.x, a01.y);                                        \
        PACK_F32X2(A23, a23.x, a23.y);                                        \
        PACK_F32X2(B01, b01.x, b01.y);                                        \
        PACK_F32X2(B23, b23.x, b23.y);                                        \
        PACK_F32X2(CW, cwf, cwf);                                             \
        MUL_F32X2(m0, WB, B01);                                               \
        FMA_F32X2(t01, WA, A01, m0);                                          \
        MUL_F32X2(m1, WB, B23);                                               \
        FMA_F32X2(t23, WA, A23, m1);                                          \
        FMA_F32X2(acc01, CW, t01, acc01);                                     \
        FMA_F32X2(acc23, CW, t23, acc23);                                     \
    }

    COLUMN(g00, c00)
    COLUMN(g01, c01)
    COLUMN(g10, c10)
    COLUMN(g11, c11)

    float r0, r1, r2, r3;
    UNPACK_F32X2(r0, r1, acc01);
    UNPACK_F32X2(r2, r3, acc23);

    const unsigned base = ((unsigned)b << 23) + tid;   // b*C*VOL + tid
    out[base]              = r0;
    out[base + (1u << 21)] = r1;
    out[base + (2u << 21)] = r2;
    out[base + (3u << 21)] = r3;
}

extern "C" void kernel_launch(void* const* d_in, const int* in_sizes, int n_in,
                              void* d_out, int out_size) {
    const float* x       = (const float*)d_in[0];
    const float* im_feat = (const float*)d_in[1];
    const float* pos_w   = (const float*)d_in[2];
    const float* pos_b   = (const float*)d_in[3];
    float* out = (float*)d_out;

    prep_kernel<<<BB * VOL / 4 / 256, 256>>>(x, im_feat, pos_w, pos_b);
    dim3 grid(VOL / 256, BB);
    sample_kernel<<<grid, 256>>>(out);
}